// round 11
// baseline (speedup 1.0000x reference)
#include <cuda_runtime.h>
#include <cuda_bf16.h>
#include <cuda_fp8.h>
#include <cstdint>

#define N_NODES 100000
#define N_EDGES 3200000
#define HID 128
#define N_GRAPHS 512

// ---------------- scratch (device globals; no allocation allowed) ----------
__device__ uint32_t g_Th[(size_t)N_NODES * 64];  // T as packed bf16x2 (128 cols)
__device__ uint32_t g_T8[(size_t)N_NODES * 32];  // T as packed e4m3 x4 (128 cols)
__device__ uint32_t g_Ah[(size_t)N_NODES * 64];  // A as packed bf16x2
__device__ float g_deg[N_NODES];
__device__ float g_dinv[N_NODES];
__device__ float g_pool[N_GRAPHS * HID];
__device__ float g_cnt[N_GRAPHS];
__device__ int   g_amax_i[4];                    // per-layer amax (float bits)
// CSR (by destination) — interleaved (src, weight_bits)
__device__ int   g_row_ptr[N_NODES + 1];
__device__ int   g_row_fill[N_NODES];
__device__ int2  g_col[N_EDGES];
__device__ int   g_hist[N_NODES];

#define SCAN_BLK 391            // ceil(100000/256)
__device__ int   g_bsum[512];   // block sums (padded)

// tf32 B-fragments for all 4 layers:
// layout [layer][s2(8)][t(16)][lane(32)] -> float4 = (b0_even, b1_even, b0_odd, b1_odd)
__device__ float4 g_Wfrag[4 * 8 * 16 * 32];

__device__ __forceinline__ uint32_t cvt_tf32(float f) {
    uint32_t u;
    asm("cvt.rna.tf32.f32 %0, %1;" : "=r"(u) : "f"(f));
    return u;
}

// ---------------- degree / norm ----------------
__global__ void k_init_deg() {
    int i = blockIdx.x * blockDim.x + threadIdx.x;
    if (i < N_NODES) { g_deg[i] = 1.0f; g_hist[i] = 0; }   // self-loop weight
}

__global__ void k_accum_deg(const int* __restrict__ ei, const float* __restrict__ ew) {
    int e = blockIdx.x * blockDim.x + threadIdx.x;
    if (e >= N_EDGES) return;
    int dst = ei[N_EDGES + e];
    atomicAdd(&g_deg[dst], ew[e]);
    atomicAdd(&g_hist[dst], 1);
}

__global__ void k_dinv() {
    int i = blockIdx.x * blockDim.x + threadIdx.x;
    if (i < N_NODES) g_dinv[i] = rsqrtf(g_deg[i]);   // deg >= 1 always
}

// ---------------- 3-phase parallel exclusive scan over g_hist --------------
__global__ void k_scan1() {
    __shared__ int sh[256];
    int i = blockIdx.x * 256 + threadIdx.x;
    int v = (i < N_NODES) ? g_hist[i] : 0;
    sh[threadIdx.x] = v;
    __syncthreads();
    #pragma unroll
    for (int o = 128; o > 0; o >>= 1) {
        if (threadIdx.x < o) sh[threadIdx.x] += sh[threadIdx.x + o];
        __syncthreads();
    }
    if (threadIdx.x == 0) g_bsum[blockIdx.x] = sh[0];
}

__global__ void k_scan2() {
    __shared__ int sh[512];
    int t = threadIdx.x;
    sh[t] = (t < SCAN_BLK) ? g_bsum[t] : 0;
    __syncthreads();
    #pragma unroll
    for (int o = 1; o < 512; o <<= 1) {
        int v = (t >= o) ? sh[t - o] : 0;
        __syncthreads();
        sh[t] += v;
        __syncthreads();
    }
    if (t < SCAN_BLK) g_bsum[t] = (t == 0) ? 0 : sh[t - 1];   // exclusive
}

__global__ void k_scan3() {
    __shared__ int sh[256];
    int t = threadIdx.x;
    int i = blockIdx.x * 256 + t;
    int v = (i < N_NODES) ? g_hist[i] : 0;
    sh[t] = v;
    __syncthreads();
    #pragma unroll
    for (int o = 1; o < 256; o <<= 1) {
        int u = (t >= o) ? sh[t - o] : 0;
        __syncthreads();
        sh[t] += u;
        __syncthreads();
    }
    if (i < N_NODES) {
        int off = g_bsum[blockIdx.x] + sh[t] - v;   // exclusive
        g_row_ptr[i] = off;
        g_row_fill[i] = off;
    }
    if (i == 0) g_row_ptr[N_NODES] = N_EDGES;
}

// ---------------- fill CSR: interleaved (src, norm-weight) -----------------
__global__ void k_fill(const int* __restrict__ ei, const float* __restrict__ ew) {
    int e = blockIdx.x * blockDim.x + threadIdx.x;
    if (e >= N_EDGES) return;
    int src = ei[e], dst = ei[N_EDGES + e];
    int pos = atomicAdd(&g_row_fill[dst], 1);
    float w = g_dinv[src] * ew[e] * g_dinv[dst];
    g_col[pos] = make_int2(src, __float_as_int(w));
}

// ---------------- precompute W tf32 fragments (all 4 layers) ---------------
__global__ void k_wfrag(const float* __restrict__ W0, const float* __restrict__ W1,
                        const float* __restrict__ W2, const float* __restrict__ W3) {
    int idx = blockIdx.x * 256 + threadIdx.x;     // 4*8*16*32 = 16384
    if (idx >= 4 * 8 * 16 * 32) return;
    int layer = idx >> 12;
    int rem = idx & 4095;
    int s2 = rem >> 9;           // k-step pair (0..7)
    int t  = (rem >> 5) & 15;    // n-tile (0..15)
    int lane = rem & 31;
    int tg = lane & 3, gid = lane >> 2;
    const float* W = (layer == 0) ? W0 : (layer == 1) ? W1 : (layer == 2) ? W2 : W3;
    int n = t * 8 + gid;
    int k0 = s2 * 16;
    float4 v;
    v.x = __uint_as_float(cvt_tf32(W[(k0 + tg) * HID + n]));
    v.y = __uint_as_float(cvt_tf32(W[(k0 + tg + 4) * HID + n]));
    v.z = __uint_as_float(cvt_tf32(W[(k0 + 8 + tg) * HID + n]));
    v.w = __uint_as_float(cvt_tf32(W[(k0 + 12 + tg) * HID + n]));
    g_Wfrag[idx] = v;
}

// ---------------- GEMM via mma.sync tf32: Th = bf16(act(in) @ W) -----------
#define GTILE 128
#define XS_STRIDE 132
#define ST_STRIDE 68   // bf16 stage stride (words); conflict-free, 16B-aligned
#define GEMM_SMEM (GTILE * XS_STRIDE * 4)

__device__ __forceinline__ void mma_tf32(float* d, uint32_t a0, uint32_t a1,
                                         uint32_t a2, uint32_t a3,
                                         float bx, float by) {
    asm volatile(
        "mma.sync.aligned.m16n8k8.row.col.f32.tf32.tf32.f32 "
        "{%0,%1,%2,%3}, {%4,%5,%6,%7}, {%8,%9}, {%0,%1,%2,%3};"
        : "+f"(d[0]), "+f"(d[1]), "+f"(d[2]), "+f"(d[3])
        : "r"(a0), "r"(a1), "r"(a2), "r"(a3),
          "r"(__float_as_uint(bx)), "r"(__float_as_uint(by)));
}

__device__ __forceinline__ uint32_t pack_bf16x2(float a, float b) {
    __nv_bfloat162 h = __float22bfloat162_rn(make_float2(a, b));
    return *(uint32_t*)&h;
}

__global__ void __launch_bounds__(256) k_gemm_mma(const float* __restrict__ X,
                                                  int layer) {
    extern __shared__ uint32_t Xs[];   // [128][132] tf32 bits; reused as bf16 stage
    int tid = threadIdx.x;
    int wid = tid >> 5;
    int lane = tid & 31;
    int row0 = blockIdx.x * GTILE;

    // stage input tile: layer 0 = fp32 x (no relu), layers 1-3 = bf16 A (+relu)
    #pragma unroll
    for (int it = 0; it < 16; it++) {
        int i = tid + it * 256;            // row = i>>5, kg = i&31
        int row = i >> 5;
        int kg = i & 31;
        int grow = row0 + row;
        float4 v = make_float4(0.f, 0.f, 0.f, 0.f);
        if (grow < N_NODES) {
            if (layer == 0) {
                v = *(const float4*)(X + (size_t)grow * HID + kg * 4);
            } else {
                uint2 p = *(const uint2*)(g_Ah + (size_t)grow * 64 + kg * 2);
                float2 lo = __bfloat1622float2(*(__nv_bfloat162*)&p.x);
                float2 hi = __bfloat1622float2(*(__nv_bfloat162*)&p.y);
                v = make_float4(fmaxf(lo.x, 0.f), fmaxf(lo.y, 0.f),
                                fmaxf(hi.x, 0.f), fmaxf(hi.y, 0.f));
            }
        }
        uint32_t* dst = Xs + row * XS_STRIDE + kg * 4;
        dst[0] = cvt_tf32(v.x); dst[1] = cvt_tf32(v.y);
        dst[2] = cvt_tf32(v.z); dst[3] = cvt_tf32(v.w);
    }
    __syncthreads();

    int tg = lane & 3, gid = lane >> 2;
    float acc[16][4];
    #pragma unroll
    for (int t = 0; t < 16; t++)
        #pragma unroll
        for (int j = 0; j < 4; j++) acc[t][j] = 0.f;

    const uint32_t* arow_lo = Xs + (wid * 16 + gid) * XS_STRIDE;
    const uint32_t* arow_hi = arow_lo + 8 * XS_STRIDE;
    const float4* frag = g_Wfrag + (size_t)layer * 4096 + lane;

    #pragma unroll
    for (int s2 = 0; s2 < 8; s2++) {
        int k0 = s2 * 16;
        uint32_t ae0 = arow_lo[k0 + tg];
        uint32_t ae1 = arow_hi[k0 + tg];
        uint32_t ae2 = arow_lo[k0 + tg + 4];
        uint32_t ae3 = arow_hi[k0 + tg + 4];
        uint32_t ao0 = arow_lo[k0 + 8 + tg];
        uint32_t ao1 = arow_hi[k0 + 8 + tg];
        uint32_t ao2 = arow_lo[k0 + 12 + tg];
        uint32_t ao3 = arow_hi[k0 + 12 + tg];
        const float4* f = frag + s2 * 512;   // [t][lane] stride 32
        #pragma unroll
        for (int t = 0; t < 16; t++) {
            float4 b = f[t * 32];
            mma_tf32(acc[t], ae0, ae1, ae2, ae3, b.x, b.y);
            mma_tf32(acc[t], ao0, ao1, ao2, ao3, b.z, b.w);
        }
    }

    // per-layer amax for fp8 quantization (OOB rows contribute 0)
    {
        float m = 0.f;
        #pragma unroll
        for (int t = 0; t < 16; t++)
            #pragma unroll
            for (int j = 0; j < 4; j++) m = fmaxf(m, fabsf(acc[t][j]));
        #pragma unroll
        for (int o = 16; o > 0; o >>= 1)
            m = fmaxf(m, __shfl_xor_sync(0xffffffffu, m, o));
        if (lane == 0) atomicMax(&g_amax_i[layer], __float_as_int(m));
    }

    // epilogue: stage bf16x2 rows in smem (conflict-free), then coalesced STG
    __syncthreads();   // all warps done reading Xs
    uint32_t* St = Xs; // reuse: [128][ST_STRIDE]
    int lrow_lo = wid * 16 + gid;
    #pragma unroll
    for (int t = 0; t < 16; t++) {
        int widx = t * 4 + tg;
        St[lrow_lo * ST_STRIDE + widx]       = pack_bf16x2(acc[t][0], acc[t][1]);
        St[(lrow_lo + 8) * ST_STRIDE + widx] = pack_bf16x2(acc[t][2], acc[t][3]);
    }
    __syncthreads();
    // copy 128 rows x 64 words = 2048 uint4 -> fully coalesced in g_Th
    #pragma unroll
    for (int it = 0; it < 8; it++) {
        int j = tid + it * 256;        // j in [0,2048): row = j>>4, w4 = j&15
        int row = j >> 4;
        int w4 = j & 15;
        int grow = row0 + row;
        if (grow < N_NODES) {
            uint4 v = *(const uint4*)&St[row * ST_STRIDE + w4 * 4];
            *(uint4*)(g_Th + (size_t)grow * 64 + w4 * 4) = v;
        }
    }
}

// ---------------- quantize bf16 T -> e4m3 fp8 (global per-layer scale) -----
__global__ void k_quant(int layer) {
    int idx = blockIdx.x * 256 + threadIdx.x;    // over N_NODES*32 fp8-words
    if (idx >= N_NODES * 32) return;
    float amax = __int_as_float(g_amax_i[layer]);
    float inv = (amax > 0.f) ? (448.f / amax) : 0.f;
    uint2 p = *(const uint2*)(g_Th + (size_t)idx * 2);
    float2 f0 = __bfloat1622float2(*(__nv_bfloat162*)&p.x);
    float2 f1 = __bfloat1622float2(*(__nv_bfloat162*)&p.y);
    f0.x *= inv; f0.y *= inv; f1.x *= inv; f1.y *= inv;
    __nv_fp8x2_storage_t q0 = __nv_cvt_float2_to_fp8x2(f0, __NV_SATFINITE, __NV_E4M3);
    __nv_fp8x2_storage_t q1 = __nv_cvt_float2_to_fp8x2(f1, __NV_SATFINITE, __NV_E4M3);
    g_T8[idx] = (uint32_t)q0 | ((uint32_t)q1 << 16);
}

// ---------------- aggregate (quarter-warp per edge, fp8 gather) ------------
__device__ __forceinline__ void deq_fma(float* acc, uint32_t v, float w) {
    __half2_raw h0 = __nv_cvt_fp8x2_to_halfraw2((__nv_fp8x2_storage_t)(v & 0xffffu), __NV_E4M3);
    __half2_raw h1 = __nv_cvt_fp8x2_to_halfraw2((__nv_fp8x2_storage_t)(v >> 16), __NV_E4M3);
    float2 f0 = __half22float2(*(__half2*)&h0);
    float2 f1 = __half22float2(*(__half2*)&h1);
    acc[0] += f0.x * w; acc[1] += f0.y * w;
    acc[2] += f1.x * w; acc[3] += f1.y * w;
}

// acc[16] = cols [sl*16 .. sl*16+15]; quarter q handles edge e+q
__device__ __forceinline__ void aggregate_core(int node, int q, int sl,
                                               const float* __restrict__ b,
                                               float gs, float* acc) {
    int beg = __ldg(&g_row_ptr[node]);
    int end = __ldg(&g_row_ptr[node + 1]);
    #pragma unroll
    for (int j = 0; j < 16; j++) acc[j] = 0.f;

    if (q == 0) {   // bias + self-loop counted once
        float di = __ldg(&g_dinv[node]);
        float sw = di * di * gs;
        uint4 r = *(const uint4*)(g_T8 + (size_t)node * 32 + sl * 4);
        const float4* b4 = (const float4*)b + sl * 4;
        #pragma unroll
        for (int k = 0; k < 4; k++) {
            float4 bb = b4[k];
            acc[k * 4 + 0] = bb.x; acc[k * 4 + 1] = bb.y;
            acc[k * 4 + 2] = bb.z; acc[k * 4 + 3] = bb.w;
        }
        deq_fma(acc + 0, r.x, sw);  deq_fma(acc + 4, r.y, sw);
        deq_fma(acc + 8, r.z, sw);  deq_fma(acc + 12, r.w, sw);
    }

    #pragma unroll 2
    for (int e = beg; e < end; e += 4) {
        int ee = e + q;
        bool act = ee < end;
        int2 c = __ldg(&g_col[act ? ee : beg]);
        float w = act ? __int_as_float(c.y) * gs : 0.f;
        uint4 r = *(const uint4*)(g_T8 + (size_t)c.x * 32 + sl * 4);
        deq_fma(acc + 0, r.x, w);   deq_fma(acc + 4, r.y, w);
        deq_fma(acc + 8, r.z, w);   deq_fma(acc + 12, r.w, w);
    }

    // merge quarter-warps: xor 8 (q0<->q1, q2<->q3), xor 16
    #pragma unroll
    for (int j = 0; j < 16; j++) {
        acc[j] += __shfl_xor_sync(0xffffffffu, acc[j], 8);
        acc[j] += __shfl_xor_sync(0xffffffffu, acc[j], 16);
    }
}

// layers 0-2: write bf16 A
__global__ void k_aggregate(const float* __restrict__ b, int layer) {
    int node = (blockIdx.x * blockDim.x + threadIdx.x) >> 5;
    int lane = threadIdx.x & 31;
    if (node >= N_NODES) return;
    int q = lane >> 3, sl = lane & 7;
    float gs = __int_as_float(g_amax_i[layer]) * (1.f / 448.f);
    float acc[16];
    aggregate_core(node, q, sl, b, gs, acc);
    if (q == 0) {
        uint4 lo, hi;
        lo.x = pack_bf16x2(acc[0], acc[1]);   lo.y = pack_bf16x2(acc[2], acc[3]);
        lo.z = pack_bf16x2(acc[4], acc[5]);   lo.w = pack_bf16x2(acc[6], acc[7]);
        hi.x = pack_bf16x2(acc[8], acc[9]);   hi.y = pack_bf16x2(acc[10], acc[11]);
        hi.z = pack_bf16x2(acc[12], acc[13]); hi.w = pack_bf16x2(acc[14], acc[15]);
        *(uint4*)(g_Ah + (size_t)node * 64 + sl * 8)     = lo;
        *(uint4*)(g_Ah + (size_t)node * 64 + sl * 8 + 4) = hi;
    }
}

// layer 3: relu + pool directly
__global__ void k_aggregate_pool(const float* __restrict__ b, int layer,
                                 const int* __restrict__ batch) {
    int node = (blockIdx.x * blockDim.x + threadIdx.x) >> 5;
    int lane = threadIdx.x & 31;
    if (node >= N_NODES) return;
    int q = lane >> 3, sl = lane & 7;
    float gs = __int_as_float(g_amax_i[layer]) * (1.f / 448.f);
    float acc[16];
    aggregate_core(node, q, sl, b, gs, acc);
    if (q == 0) {
        #pragma unroll
        for (int j = 0; j < 16; j++) acc[j] = fmaxf(acc[j], 0.f);
        int g = __ldg(&batch[node]);
        float* d = g_pool + g * HID + sl * 16;
        #pragma unroll
        for (int k = 0; k < 4; k++) {
            asm volatile("red.global.add.v4.f32 [%0], {%1,%2,%3,%4};"
                         :: "l"(d + k * 4), "f"(acc[k * 4 + 0]), "f"(acc[k * 4 + 1]),
                            "f"(acc[k * 4 + 2]), "f"(acc[k * 4 + 3]) : "memory");
        }
        if (lane == 0) atomicAdd(&g_cnt[g], 1.0f);
    }
}

// ---------------- pooling buffers + amax zero ----------------
__global__ void k_zero_pool() {
    int i = blockIdx.x * blockDim.x + threadIdx.x;
    if (i < N_GRAPHS * HID) g_pool[i] = 0.f;
    if (i < N_GRAPHS) g_cnt[i] = 0.f;
    if (i < 4) g_amax_i[i] = 0;
}

// ---------------- head ----------------
__global__ void k_final(const float* __restrict__ Wc, const float* __restrict__ bc,
                        float* __restrict__ out) {
    int g = blockIdx.x;
    int c = threadIdx.x;     // 128
    float cn = fmaxf(g_cnt[g], 1.0f);
    float v = g_pool[g * HID + c] / cn * Wc[c];
    #pragma unroll
    for (int o = 16; o > 0; o >>= 1) v += __shfl_down_sync(0xffffffffu, v, o);
    __shared__ float ss[4];
    if ((c & 31) == 0) ss[c >> 5] = v;
    __syncthreads();
    if (c == 0) {
        float s = ss[0] + ss[1] + ss[2] + ss[3] + bc[0];
        out[g] = 1.0f / (1.0f + expf(-s));
    }
}

// ---------------- launch ----------------
extern "C" void kernel_launch(void* const* d_in, const int* in_sizes, int n_in,
                              void* d_out, int out_size) {
    const float* x   = (const float*)d_in[0];
    const int*   ei  = (const int*)d_in[1];
    const float* ew  = (const float*)d_in[2];
    const int*   bat = (const int*)d_in[3];
    const float* W[4]  = { (const float*)d_in[4], (const float*)d_in[6],
                           (const float*)d_in[8], (const float*)d_in[10] };
    const float* B[4]  = { (const float*)d_in[5], (const float*)d_in[7],
                           (const float*)d_in[9], (const float*)d_in[11] };
    const float* Wc  = (const float*)d_in[12];
    const float* bc  = (const float*)d_in[13];
    float* out = (float*)d_out;

    cudaFuncSetAttribute(k_gemm_mma, cudaFuncAttributeMaxDynamicSharedMemorySize,
                         GEMM_SMEM);

    // ---- preprocessing: degrees + CSR build + W fragments + pool/amax zero ----
    k_init_deg<<<(N_NODES + 255) / 256, 256>>>();
    k_accum_deg<<<(N_EDGES + 255) / 256, 256>>>(ei, ew);
    k_dinv<<<(N_NODES + 255) / 256, 256>>>();
    k_scan1<<<SCAN_BLK, 256>>>();
    k_scan2<<<1, 512>>>();
    k_scan3<<<SCAN_BLK, 256>>>();
    k_fill<<<(N_EDGES + 255) / 256, 256>>>(ei, ew);
    k_wfrag<<<64, 256>>>(W[0], W[1], W[2], W[3]);
    k_zero_pool<<<(N_GRAPHS * HID + 255) / 256, 256>>>();

    const int gemm_grid = (N_NODES + GTILE - 1) / GTILE;     // 782
    const int aggr_grid = (N_NODES * 32 + 255) / 256;        // warp per node
    const int quant_grid = (N_NODES * 32 + 255) / 256;       // word per thread

    // ---- 4 GCN layers (last one fuses relu+pool) ----
    for (int l = 0; l < 4; l++) {
        k_gemm_mma<<<gemm_grid, 256, GEMM_SMEM>>>(x, l);
        k_quant<<<quant_grid, 256>>>(l);
        if (l < 3)
            k_aggregate<<<aggr_grid, 256>>>(B[l], l);
        else
            k_aggregate_pool<<<aggr_grid, 256>>>(B[l], l, bat);
    }

    // ---- head ----
    k_final<<<N_GRAPHS, HID>>>(Wc, bc, out);
}

// round 12
// speedup vs baseline: 1.0585x; 1.0585x over previous
#include <cuda_runtime.h>
#include <cuda_bf16.h>
#include <cuda_fp8.h>
#include <cstdint>

#define N_NODES 100000
#define N_EDGES 3200000
#define HID 128
#define N_GRAPHS 512

// ---------------- scratch (device globals; no allocation allowed) ----------
__device__ uint32_t g_Th[(size_t)N_NODES * 64];  // T as packed bf16x2 (128 cols)
__device__ uint32_t g_T8[(size_t)N_NODES * 32];  // T as packed e4m3 x4 (128 cols)
__device__ uint32_t g_Ah[(size_t)N_NODES * 64];  // A as packed bf16x2
__device__ float g_deg[N_NODES];
__device__ float g_dinv[N_NODES];
__device__ float g_pool[N_GRAPHS * HID];
__device__ float g_cnt[N_GRAPHS];
__device__ int   g_amax_i[4];                    // per-layer amax (float bits)
// CSR (by destination) — interleaved (src, weight_bits)
__device__ int   g_row_ptr[N_NODES + 1];
__device__ int   g_row_fill[N_NODES];
__device__ int2  g_col[N_EDGES];
__device__ int   g_hist[N_NODES];

#define SCAN_BLK 391            // ceil(100000/256)
__device__ int   g_bsum[512];   // block sums (padded)

// tf32 B-fragments for all 4 layers:
// layout [layer][s2(8)][t(16)][lane(32)] -> float4 = (b0_even, b1_even, b0_odd, b1_odd)
__device__ float4 g_Wfrag[4 * 8 * 16 * 32];

__device__ __forceinline__ uint32_t cvt_tf32(float f) {
    uint32_t u;
    asm("cvt.rna.tf32.f32 %0, %1;" : "=r"(u) : "f"(f));
    return u;
}

// ---------------- degree / norm ----------------
__global__ void k_init_deg() {
    int i = blockIdx.x * blockDim.x + threadIdx.x;
    if (i < N_NODES) { g_deg[i] = 1.0f; g_hist[i] = 0; }   // self-loop weight
}

__global__ void k_accum_deg(const int* __restrict__ ei, const float* __restrict__ ew) {
    int e = blockIdx.x * blockDim.x + threadIdx.x;
    if (e >= N_EDGES) return;
    int dst = ei[N_EDGES + e];
    atomicAdd(&g_deg[dst], ew[e]);
    atomicAdd(&g_hist[dst], 1);
}

__global__ void k_dinv() {
    int i = blockIdx.x * blockDim.x + threadIdx.x;
    if (i < N_NODES) g_dinv[i] = rsqrtf(g_deg[i]);   // deg >= 1 always
}

// ---------------- 3-phase parallel exclusive scan over g_hist --------------
__global__ void k_scan1() {
    __shared__ int sh[256];
    int i = blockIdx.x * 256 + threadIdx.x;
    int v = (i < N_NODES) ? g_hist[i] : 0;
    sh[threadIdx.x] = v;
    __syncthreads();
    #pragma unroll
    for (int o = 128; o > 0; o >>= 1) {
        if (threadIdx.x < o) sh[threadIdx.x] += sh[threadIdx.x + o];
        __syncthreads();
    }
    if (threadIdx.x == 0) g_bsum[blockIdx.x] = sh[0];
}

__global__ void k_scan2() {
    __shared__ int sh[512];
    int t = threadIdx.x;
    sh[t] = (t < SCAN_BLK) ? g_bsum[t] : 0;
    __syncthreads();
    #pragma unroll
    for (int o = 1; o < 512; o <<= 1) {
        int v = (t >= o) ? sh[t - o] : 0;
        __syncthreads();
        sh[t] += v;
        __syncthreads();
    }
    if (t < SCAN_BLK) g_bsum[t] = (t == 0) ? 0 : sh[t - 1];   // exclusive
}

__global__ void k_scan3() {
    __shared__ int sh[256];
    int t = threadIdx.x;
    int i = blockIdx.x * 256 + t;
    int v = (i < N_NODES) ? g_hist[i] : 0;
    sh[t] = v;
    __syncthreads();
    #pragma unroll
    for (int o = 1; o < 256; o <<= 1) {
        int u = (t >= o) ? sh[t - o] : 0;
        __syncthreads();
        sh[t] += u;
        __syncthreads();
    }
    if (i < N_NODES) {
        int off = g_bsum[blockIdx.x] + sh[t] - v;   // exclusive
        g_row_ptr[i] = off;
        g_row_fill[i] = off;
    }
    if (i == 0) g_row_ptr[N_NODES] = N_EDGES;
}

// ---------------- fill CSR: interleaved (src, norm-weight) -----------------
__global__ void k_fill(const int* __restrict__ ei, const float* __restrict__ ew) {
    int e = blockIdx.x * blockDim.x + threadIdx.x;
    if (e >= N_EDGES) return;
    int src = ei[e], dst = ei[N_EDGES + e];
    int pos = atomicAdd(&g_row_fill[dst], 1);
    float w = g_dinv[src] * ew[e] * g_dinv[dst];
    g_col[pos] = make_int2(src, __float_as_int(w));
}

// ---------------- precompute W tf32 fragments (all 4 layers) ---------------
__global__ void k_wfrag(const float* __restrict__ W0, const float* __restrict__ W1,
                        const float* __restrict__ W2, const float* __restrict__ W3) {
    int idx = blockIdx.x * 256 + threadIdx.x;     // 4*8*16*32 = 16384
    if (idx >= 4 * 8 * 16 * 32) return;
    int layer = idx >> 12;
    int rem = idx & 4095;
    int s2 = rem >> 9;           // k-step pair (0..7)
    int t  = (rem >> 5) & 15;    // n-tile (0..15)
    int lane = rem & 31;
    int tg = lane & 3, gid = lane >> 2;
    const float* W = (layer == 0) ? W0 : (layer == 1) ? W1 : (layer == 2) ? W2 : W3;
    int n = t * 8 + gid;
    int k0 = s2 * 16;
    float4 v;
    v.x = __uint_as_float(cvt_tf32(W[(k0 + tg) * HID + n]));
    v.y = __uint_as_float(cvt_tf32(W[(k0 + tg + 4) * HID + n]));
    v.z = __uint_as_float(cvt_tf32(W[(k0 + 8 + tg) * HID + n]));
    v.w = __uint_as_float(cvt_tf32(W[(k0 + 12 + tg) * HID + n]));
    g_Wfrag[idx] = v;
}

// ---------------- GEMM via mma.sync tf32: Th = bf16(act(in) @ W) -----------
#define GTILE 128
#define XS_STRIDE 132
#define ST_STRIDE 68   // bf16 stage stride (words); conflict-free, 16B-aligned
#define GEMM_SMEM (GTILE * XS_STRIDE * 4)

__device__ __forceinline__ void mma_tf32(float* d, uint32_t a0, uint32_t a1,
                                         uint32_t a2, uint32_t a3,
                                         float bx, float by) {
    asm volatile(
        "mma.sync.aligned.m16n8k8.row.col.f32.tf32.tf32.f32 "
        "{%0,%1,%2,%3}, {%4,%5,%6,%7}, {%8,%9}, {%0,%1,%2,%3};"
        : "+f"(d[0]), "+f"(d[1]), "+f"(d[2]), "+f"(d[3])
        : "r"(a0), "r"(a1), "r"(a2), "r"(a3),
          "r"(__float_as_uint(bx)), "r"(__float_as_uint(by)));
}

__device__ __forceinline__ uint32_t pack_bf16x2(float a, float b) {
    __nv_bfloat162 h = __float22bfloat162_rn(make_float2(a, b));
    return *(uint32_t*)&h;
}

__global__ void __launch_bounds__(256) k_gemm_mma(const float* __restrict__ X,
                                                  int layer) {
    extern __shared__ uint32_t Xs[];   // [128][132] tf32 bits; reused as bf16 stage
    int tid = threadIdx.x;
    int wid = tid >> 5;
    int lane = tid & 31;
    int row0 = blockIdx.x * GTILE;

    // stage input tile: layer 0 = fp32 x (no relu), layers 1-3 = bf16 A (+relu)
    #pragma unroll
    for (int it = 0; it < 16; it++) {
        int i = tid + it * 256;            // row = i>>5, kg = i&31
        int row = i >> 5;
        int kg = i & 31;
        int grow = row0 + row;
        float4 v = make_float4(0.f, 0.f, 0.f, 0.f);
        if (grow < N_NODES) {
            if (layer == 0) {
                v = *(const float4*)(X + (size_t)grow * HID + kg * 4);
            } else {
                uint2 p = *(const uint2*)(g_Ah + (size_t)grow * 64 + kg * 2);
                float2 lo = __bfloat1622float2(*(__nv_bfloat162*)&p.x);
                float2 hi = __bfloat1622float2(*(__nv_bfloat162*)&p.y);
                v = make_float4(fmaxf(lo.x, 0.f), fmaxf(lo.y, 0.f),
                                fmaxf(hi.x, 0.f), fmaxf(hi.y, 0.f));
            }
        }
        uint32_t* dst = Xs + row * XS_STRIDE + kg * 4;
        dst[0] = cvt_tf32(v.x); dst[1] = cvt_tf32(v.y);
        dst[2] = cvt_tf32(v.z); dst[3] = cvt_tf32(v.w);
    }
    __syncthreads();

    int tg = lane & 3, gid = lane >> 2;
    float acc[16][4];
    #pragma unroll
    for (int t = 0; t < 16; t++)
        #pragma unroll
        for (int j = 0; j < 4; j++) acc[t][j] = 0.f;

    const uint32_t* arow_lo = Xs + (wid * 16 + gid) * XS_STRIDE;
    const uint32_t* arow_hi = arow_lo + 8 * XS_STRIDE;
    const float4* frag = g_Wfrag + (size_t)layer * 4096 + lane;

    #pragma unroll
    for (int s2 = 0; s2 < 8; s2++) {
        int k0 = s2 * 16;
        uint32_t ae0 = arow_lo[k0 + tg];
        uint32_t ae1 = arow_hi[k0 + tg];
        uint32_t ae2 = arow_lo[k0 + tg + 4];
        uint32_t ae3 = arow_hi[k0 + tg + 4];
        uint32_t ao0 = arow_lo[k0 + 8 + tg];
        uint32_t ao1 = arow_hi[k0 + 8 + tg];
        uint32_t ao2 = arow_lo[k0 + 12 + tg];
        uint32_t ao3 = arow_hi[k0 + 12 + tg];
        const float4* f = frag + s2 * 512;   // [t][lane] stride 32
        #pragma unroll
        for (int t = 0; t < 16; t++) {
            float4 b = f[t * 32];
            mma_tf32(acc[t], ae0, ae1, ae2, ae3, b.x, b.y);
            mma_tf32(acc[t], ao0, ao1, ao2, ao3, b.z, b.w);
        }
    }

    // per-layer amax for fp8 quantization (OOB rows contribute 0)
    {
        float m = 0.f;
        #pragma unroll
        for (int t = 0; t < 16; t++)
            #pragma unroll
            for (int j = 0; j < 4; j++) m = fmaxf(m, fabsf(acc[t][j]));
        #pragma unroll
        for (int o = 16; o > 0; o >>= 1)
            m = fmaxf(m, __shfl_xor_sync(0xffffffffu, m, o));
        if (lane == 0) atomicMax(&g_amax_i[layer], __float_as_int(m));
    }

    // epilogue: stage bf16x2 rows in smem (conflict-free), then coalesced STG
    __syncthreads();   // all warps done reading Xs
    uint32_t* St = Xs; // reuse: [128][ST_STRIDE]
    int lrow_lo = wid * 16 + gid;
    #pragma unroll
    for (int t = 0; t < 16; t++) {
        int widx = t * 4 + tg;
        St[lrow_lo * ST_STRIDE + widx]       = pack_bf16x2(acc[t][0], acc[t][1]);
        St[(lrow_lo + 8) * ST_STRIDE + widx] = pack_bf16x2(acc[t][2], acc[t][3]);
    }
    __syncthreads();
    // copy 128 rows x 64 words = 2048 uint4 -> fully coalesced in g_Th
    #pragma unroll
    for (int it = 0; it < 8; it++) {
        int j = tid + it * 256;        // j in [0,2048): row = j>>4, w4 = j&15
        int row = j >> 4;
        int w4 = j & 15;
        int grow = row0 + row;
        if (grow < N_NODES) {
            uint4 v = *(const uint4*)&St[row * ST_STRIDE + w4 * 4];
            *(uint4*)(g_Th + (size_t)grow * 64 + w4 * 4) = v;
        }
    }
}

// ---------------- quantize bf16 T -> e4m3 fp8 (global per-layer scale) -----
__global__ void k_quant(int layer) {
    int idx = blockIdx.x * 256 + threadIdx.x;    // over N_NODES*32 fp8-words
    if (idx >= N_NODES * 32) return;
    float amax = __int_as_float(g_amax_i[layer]);
    float inv = (amax > 0.f) ? (448.f / amax) : 0.f;
    uint2 p = *(const uint2*)(g_Th + (size_t)idx * 2);
    float2 f0 = __bfloat1622float2(*(__nv_bfloat162*)&p.x);
    float2 f1 = __bfloat1622float2(*(__nv_bfloat162*)&p.y);
    f0.x *= inv; f0.y *= inv; f1.x *= inv; f1.y *= inv;
    __nv_fp8x2_storage_t q0 = __nv_cvt_float2_to_fp8x2(f0, __NV_SATFINITE, __NV_E4M3);
    __nv_fp8x2_storage_t q1 = __nv_cvt_float2_to_fp8x2(f1, __NV_SATFINITE, __NV_E4M3);
    g_T8[idx] = (uint32_t)q0 | ((uint32_t)q1 << 16);
}

// ---------------- aggregate: warp per node, lane owns 4 cols (fp8 word) ----
__device__ __forceinline__ void deq_fma4(float4& acc, uint32_t v, float w) {
    __half2_raw h0 = __nv_cvt_fp8x2_to_halfraw2((__nv_fp8x2_storage_t)(v & 0xffffu), __NV_E4M3);
    __half2_raw h1 = __nv_cvt_fp8x2_to_halfraw2((__nv_fp8x2_storage_t)(v >> 16), __NV_E4M3);
    float2 f0 = __half22float2(*(__half2*)&h0);
    float2 f1 = __half22float2(*(__half2*)&h1);
    acc.x += f0.x * w; acc.y += f0.y * w; acc.z += f1.x * w; acc.w += f1.y * w;
}

__device__ __forceinline__ float4 aggregate_row(int node, int lane,
                                                const float* __restrict__ b,
                                                float gs) {
    int beg = __ldg(&g_row_ptr[node]);
    int end = __ldg(&g_row_ptr[node + 1]);
    float di = __ldg(&g_dinv[node]);

    // unscaled sum (fp8 units); gs applied once at the end
    float4 s = make_float4(0.f, 0.f, 0.f, 0.f);
    uint32_t ts = __ldg(&g_T8[(size_t)node * 32 + lane]);
    deq_fma4(s, ts, di * di);

    int e = beg;
    for (; e + 4 <= end; e += 4) {
        int2 c0 = __ldg(&g_col[e + 0]);
        int2 c1 = __ldg(&g_col[e + 1]);
        int2 c2 = __ldg(&g_col[e + 2]);
        int2 c3 = __ldg(&g_col[e + 3]);
        uint32_t v0 = __ldg(&g_T8[(size_t)c0.x * 32 + lane]);
        uint32_t v1 = __ldg(&g_T8[(size_t)c1.x * 32 + lane]);
        uint32_t v2 = __ldg(&g_T8[(size_t)c2.x * 32 + lane]);
        uint32_t v3 = __ldg(&g_T8[(size_t)c3.x * 32 + lane]);
        deq_fma4(s, v0, __int_as_float(c0.y));
        deq_fma4(s, v1, __int_as_float(c1.y));
        deq_fma4(s, v2, __int_as_float(c2.y));
        deq_fma4(s, v3, __int_as_float(c3.y));
    }
    for (; e < end; e++) {
        int2 c = __ldg(&g_col[e]);
        uint32_t v = __ldg(&g_T8[(size_t)c.x * 32 + lane]);
        deq_fma4(s, v, __int_as_float(c.y));
    }

    float4 bb = ((const float4*)b)[lane];
    return make_float4(bb.x + s.x * gs, bb.y + s.y * gs,
                       bb.z + s.z * gs, bb.w + s.w * gs);
}

// layers 0-2: write bf16 A
__global__ void k_aggregate(const float* __restrict__ b, int layer) {
    int node = (blockIdx.x * blockDim.x + threadIdx.x) >> 5;
    int lane = threadIdx.x & 31;
    if (node >= N_NODES) return;
    float gs = __int_as_float(g_amax_i[layer]) * (1.f / 448.f);
    float4 acc = aggregate_row(node, lane, b, gs);
    uint2 p;
    p.x = pack_bf16x2(acc.x, acc.y);
    p.y = pack_bf16x2(acc.z, acc.w);
    *(uint2*)(g_Ah + (size_t)node * 64 + lane * 2) = p;
}

// layer 3: relu + pool directly
__global__ void k_aggregate_pool(const float* __restrict__ b, int layer,
                                 const int* __restrict__ batch) {
    int node = (blockIdx.x * blockDim.x + threadIdx.x) >> 5;
    int lane = threadIdx.x & 31;
    if (node >= N_NODES) return;
    float gs = __int_as_float(g_amax_i[layer]) * (1.f / 448.f);
    float4 acc = aggregate_row(node, lane, b, gs);
    acc.x = fmaxf(acc.x, 0.f); acc.y = fmaxf(acc.y, 0.f);
    acc.z = fmaxf(acc.z, 0.f); acc.w = fmaxf(acc.w, 0.f);
    int g = __ldg(&batch[node]);
    float* d = g_pool + g * HID + lane * 4;
    asm volatile("red.global.add.v4.f32 [%0], {%1,%2,%3,%4};"
                 :: "l"(d), "f"(acc.x), "f"(acc.y), "f"(acc.z), "f"(acc.w) : "memory");
    if (lane == 0) atomicAdd(&g_cnt[g], 1.0f);
}

// ---------------- pooling buffers + amax zero ----------------
__global__ void k_zero_pool() {
    int i = blockIdx.x * blockDim.x + threadIdx.x;
    if (i < N_GRAPHS * HID) g_pool[i] = 0.f;
    if (i < N_GRAPHS) g_cnt[i] = 0.f;
    if (i < 4) g_amax_i[i] = 0;
}

// ---------------- head ----------------
__global__ void k_final(const float* __restrict__ Wc, const float* __restrict__ bc,
                        float* __restrict__ out) {
    int g = blockIdx.x;
    int c = threadIdx.x;     // 128
    float cn = fmaxf(g_cnt[g], 1.0f);
    float v = g_pool[g * HID + c] / cn * Wc[c];
    #pragma unroll
    for (int o = 16; o > 0; o >>= 1) v += __shfl_down_sync(0xffffffffu, v, o);
    __shared__ float ss[4];
    if ((c & 31) == 0) ss[c >> 5] = v;
    __syncthreads();
    if (c == 0) {
        float s = ss[0] + ss[1] + ss[2] + ss[3] + bc[0];
        out[g] = 1.0f / (1.0f + expf(-s));
    }
}

// ---------------- launch ----------------
extern "C" void kernel_launch(void* const* d_in, const int* in_sizes, int n_in,
                              void* d_out, int out_size) {
    const float* x   = (const float*)d_in[0];
    const int*   ei  = (const int*)d_in[1];
    const float* ew  = (const float*)d_in[2];
    const int*   bat = (const int*)d_in[3];
    const float* W[4]  = { (const float*)d_in[4], (const float*)d_in[6],
                           (const float*)d_in[8], (const float*)d_in[10] };
    const float* B[4]  = { (const float*)d_in[5], (const float*)d_in[7],
                           (const float*)d_in[9], (const float*)d_in[11] };
    const float* Wc  = (const float*)d_in[12];
    const float* bc  = (const float*)d_in[13];
    float* out = (float*)d_out;

    cudaFuncSetAttribute(k_gemm_mma, cudaFuncAttributeMaxDynamicSharedMemorySize,
                         GEMM_SMEM);

    // ---- preprocessing: degrees + CSR build + W fragments + pool/amax zero ----
    k_init_deg<<<(N_NODES + 255) / 256, 256>>>();
    k_accum_deg<<<(N_EDGES + 255) / 256, 256>>>(ei, ew);
    k_dinv<<<(N_NODES + 255) / 256, 256>>>();
    k_scan1<<<SCAN_BLK, 256>>>();
    k_scan2<<<1, 512>>>();
    k_scan3<<<SCAN_BLK, 256>>>();
    k_fill<<<(N_EDGES + 255) / 256, 256>>>(ei, ew);
    k_wfrag<<<64, 256>>>(W[0], W[1], W[2], W[3]);
    k_zero_pool<<<(N_GRAPHS * HID + 255) / 256, 256>>>();

    const int gemm_grid = (N_NODES + GTILE - 1) / GTILE;     // 782
    const int aggr_grid = (N_NODES * 32 + 255) / 256;        // warp per node
    const int quant_grid = (N_NODES * 32 + 255) / 256;       // word per thread

    // ---- 4 GCN layers (last one fuses relu+pool) ----
    for (int l = 0; l < 4; l++) {
        k_gemm_mma<<<gemm_grid, 256, GEMM_SMEM>>>(x, l);
        k_quant<<<quant_grid, 256>>>(l);
        if (l < 3)
            k_aggregate<<<aggr_grid, 256>>>(B[l], l);
        else
            k_aggregate_pool<<<aggr_grid, 256>>>(B[l], l, bat);
    }

    // ---- head ----
    k_final<<<N_GRAPHS, HID>>>(Wc, bc, out);
}

// round 14
// speedup vs baseline: 1.8059x; 1.7061x over previous
#include <cuda_runtime.h>
#include <cuda_bf16.h>
#include <cstdint>

#define N_NODES 100000
#define N_EDGES 3200000
#define HID 128
#define N_GRAPHS 512

// ---------------- scratch (device globals; no allocation allowed) ----------
__device__ uint32_t g_Th[(size_t)N_NODES * 64];  // T as packed bf16x2 (128 cols)
__device__ uint32_t g_Ah[(size_t)N_NODES * 64];  // A as packed bf16x2
__device__ float g_deg[N_NODES];
__device__ float g_dinv[N_NODES];
__device__ float g_pool[N_GRAPHS * HID];
__device__ float g_cnt[N_GRAPHS];
// CSR (by destination) — interleaved (src, weight_bits)
__device__ int   g_row_ptr[N_NODES + 1];
__device__ int   g_row_fill[N_NODES];
__device__ int2  g_col[N_EDGES];
__device__ int   g_hist[N_NODES];

#define SCAN_BLK 391            // ceil(100000/256)
__device__ int   g_bsum[512];   // block sums (padded)

// bf16 B-fragments for all 4 layers (m16n8k16):
// [layer][s(8)][t(16)][lane(32)] -> uint2 = (b0 = W[k0+2tg..+1][n], b1 = W[k0+8+2tg..+1][n])
__device__ uint2 g_Wfrag[4 * 8 * 16 * 32];

__device__ __forceinline__ uint32_t pack_bf16x2(float a, float b) {
    __nv_bfloat162 h = __float22bfloat162_rn(make_float2(a, b));
    return *(uint32_t*)&h;
}

// ---------------- degree / norm ----------------
__global__ void k_init_deg() {
    int i = blockIdx.x * blockDim.x + threadIdx.x;
    if (i < N_NODES) { g_deg[i] = 1.0f; g_hist[i] = 0; }   // self-loop weight
}

__global__ void k_accum_deg(const int* __restrict__ ei, const float* __restrict__ ew) {
    int e = blockIdx.x * blockDim.x + threadIdx.x;
    if (e >= N_EDGES) return;
    int dst = ei[N_EDGES + e];
    atomicAdd(&g_deg[dst], ew[e]);
    atomicAdd(&g_hist[dst], 1);
}

__global__ void k_dinv() {
    int i = blockIdx.x * blockDim.x + threadIdx.x;
    if (i < N_NODES) g_dinv[i] = rsqrtf(g_deg[i]);   // deg >= 1 always
}

// ---------------- 3-phase parallel exclusive scan over g_hist --------------
__global__ void k_scan1() {
    __shared__ int sh[256];
    int i = blockIdx.x * 256 + threadIdx.x;
    int v = (i < N_NODES) ? g_hist[i] : 0;
    sh[threadIdx.x] = v;
    __syncthreads();
    #pragma unroll
    for (int o = 128; o > 0; o >>= 1) {
        if (threadIdx.x < o) sh[threadIdx.x] += sh[threadIdx.x + o];
        __syncthreads();
    }
    if (threadIdx.x == 0) g_bsum[blockIdx.x] = sh[0];
}

__global__ void k_scan2() {
    __shared__ int sh[512];
    int t = threadIdx.x;
    sh[t] = (t < SCAN_BLK) ? g_bsum[t] : 0;
    __syncthreads();
    #pragma unroll
    for (int o = 1; o < 512; o <<= 1) {
        int v = (t >= o) ? sh[t - o] : 0;
        __syncthreads();
        sh[t] += v;
        __syncthreads();
    }
    if (t < SCAN_BLK) g_bsum[t] = (t == 0) ? 0 : sh[t - 1];   // exclusive
}

__global__ void k_scan3() {
    __shared__ int sh[256];
    int t = threadIdx.x;
    int i = blockIdx.x * 256 + t;
    int v = (i < N_NODES) ? g_hist[i] : 0;
    sh[t] = v;
    __syncthreads();
    #pragma unroll
    for (int o = 1; o < 256; o <<= 1) {
        int u = (t >= o) ? sh[t - o] : 0;
        __syncthreads();
        sh[t] += u;
        __syncthreads();
    }
    if (i < N_NODES) {
        int off = g_bsum[blockIdx.x] + sh[t] - v;   // exclusive
        g_row_ptr[i] = off;
        g_row_fill[i] = off;
    }
    if (i == 0) g_row_ptr[N_NODES] = N_EDGES;
}

// ---------------- fill CSR: interleaved (src, norm-weight) -----------------
__global__ void k_fill(const int* __restrict__ ei, const float* __restrict__ ew) {
    int e = blockIdx.x * blockDim.x + threadIdx.x;
    if (e >= N_EDGES) return;
    int src = ei[e], dst = ei[N_EDGES + e];
    int pos = atomicAdd(&g_row_fill[dst], 1);
    float w = g_dinv[src] * ew[e] * g_dinv[dst];
    g_col[pos] = make_int2(src, __float_as_int(w));
}

// ---------------- precompute W bf16 fragments (all 4 layers) ---------------
__global__ void k_wfrag(const float* __restrict__ W0, const float* __restrict__ W1,
                        const float* __restrict__ W2, const float* __restrict__ W3) {
    int idx = blockIdx.x * 256 + threadIdx.x;     // 4*8*16*32 = 16384
    if (idx >= 4 * 8 * 16 * 32) return;
    int layer = idx >> 12;
    int rem = idx & 4095;
    int s = rem >> 9;            // k-step (0..7), K=16 each
    int t = (rem >> 5) & 15;     // n-tile (0..15)
    int lane = rem & 31;
    int tg = lane & 3, gid = lane >> 2;
    const float* W = (layer == 0) ? W0 : (layer == 1) ? W1 : (layer == 2) ? W2 : W3;
    int n = t * 8 + gid;
    int k0 = s * 16;
    uint2 v;
    v.x = pack_bf16x2(W[(k0 + 2 * tg) * HID + n],     W[(k0 + 2 * tg + 1) * HID + n]);
    v.y = pack_bf16x2(W[(k0 + 8 + 2 * tg) * HID + n], W[(k0 + 9 + 2 * tg) * HID + n]);
    g_Wfrag[idx] = v;
}

// ---------------- GEMM via mma.sync bf16 m16n8k16: Th = bf16(act(in) @ W) --
#define GTILE 128
#define XS_STRIDE 68   // bf16x2 words per row (64 + pad 4); conflict-free
#define GEMM_SMEM (GTILE * XS_STRIDE * 4)

__device__ __forceinline__ void mma_bf16(float* d, uint32_t a0, uint32_t a1,
                                         uint32_t a2, uint32_t a3,
                                         uint32_t b0, uint32_t b1) {
    asm volatile(
        "mma.sync.aligned.m16n8k16.row.col.f32.bf16.bf16.f32 "
        "{%0,%1,%2,%3}, {%4,%5,%6,%7}, {%8,%9}, {%0,%1,%2,%3};"
        : "+f"(d[0]), "+f"(d[1]), "+f"(d[2]), "+f"(d[3])
        : "r"(a0), "r"(a1), "r"(a2), "r"(a3), "r"(b0), "r"(b1));
}

__global__ void __launch_bounds__(256) k_gemm_mma(const float* __restrict__ X,
                                                  int layer) {
    extern __shared__ uint32_t Xs[];   // [128][68] bf16x2 words; reused as out stage
    int tid = threadIdx.x;
    int wid = tid >> 5;
    int lane = tid & 31;
    int row0 = blockIdx.x * GTILE;

    // stage input tile as bf16x2 (FULL 128 cols = 32 word-pairs per row):
    // layer 0 = fp32 x; layers 1-3 = bf16 A (+relu)
    #pragma unroll
    for (int it = 0; it < 16; it++) {
        int i = tid + it * 256;            // i in [0,4096): row = i>>5, wp = i&31
        int row = i >> 5;
        int wp = i & 31;                   // word-pair -> cols 4wp..4wp+3
        int grow = row0 + row;
        uint32_t w0 = 0, w1 = 0;
        if (grow < N_NODES) {
            if (layer == 0) {
                float4 v = *(const float4*)(X + (size_t)grow * HID + wp * 4);
                w0 = pack_bf16x2(v.x, v.y);
                w1 = pack_bf16x2(v.z, v.w);
            } else {
                uint2 p = *(const uint2*)(g_Ah + (size_t)grow * 64 + wp * 2);
                float2 lo = __bfloat1622float2(*(__nv_bfloat162*)&p.x);
                float2 hi = __bfloat1622float2(*(__nv_bfloat162*)&p.y);
                w0 = pack_bf16x2(fmaxf(lo.x, 0.f), fmaxf(lo.y, 0.f));
                w1 = pack_bf16x2(fmaxf(hi.x, 0.f), fmaxf(hi.y, 0.f));
            }
        }
        Xs[row * XS_STRIDE + wp * 2]     = w0;
        Xs[row * XS_STRIDE + wp * 2 + 1] = w1;
    }
    __syncthreads();

    int tg = lane & 3, gid = lane >> 2;
    float acc[16][4];
    #pragma unroll
    for (int t = 0; t < 16; t++)
        #pragma unroll
        for (int j = 0; j < 4; j++) acc[t][j] = 0.f;

    const uint32_t* arow_lo = Xs + (wid * 16 + gid) * XS_STRIDE;
    const uint32_t* arow_hi = arow_lo + 8 * XS_STRIDE;
    const uint2* frag = g_Wfrag + (size_t)layer * 4096 + lane;

    #pragma unroll
    for (int s = 0; s < 8; s++) {
        int kw = s * 8;   // word base for this k-step (16 cols = 8 words)
        uint32_t a0 = arow_lo[kw + tg];
        uint32_t a1 = arow_hi[kw + tg];
        uint32_t a2 = arow_lo[kw + 4 + tg];
        uint32_t a3 = arow_hi[kw + 4 + tg];
        const uint2* f = frag + s * 512;   // [t][lane] stride 32
        #pragma unroll
        for (int t = 0; t < 16; t++) {
            uint2 b = f[t * 32];
            mma_bf16(acc[t], a0, a1, a2, a3, b.x, b.y);
        }
    }

    // epilogue: stage bf16x2 rows in smem (conflict-free), then coalesced STG
    __syncthreads();   // all warps done reading Xs
    uint32_t* St = Xs; // reuse: [128][XS_STRIDE]
    int lrow_lo = wid * 16 + gid;
    #pragma unroll
    for (int t = 0; t < 16; t++) {
        int widx = t * 4 + tg;
        St[lrow_lo * XS_STRIDE + widx]       = pack_bf16x2(acc[t][0], acc[t][1]);
        St[(lrow_lo + 8) * XS_STRIDE + widx] = pack_bf16x2(acc[t][2], acc[t][3]);
    }
    __syncthreads();
    // copy 128 rows x 64 words = 2048 uint4 -> fully coalesced in g_Th
    #pragma unroll
    for (int it = 0; it < 8; it++) {
        int j = tid + it * 256;        // j in [0,2048): row = j>>4, w4 = j&15
        int row = j >> 4;
        int w4 = j & 15;
        int grow = row0 + row;
        if (grow < N_NODES) {
            uint4 v = *(const uint4*)&St[row * XS_STRIDE + w4 * 4];
            *(uint4*)(g_Th + (size_t)grow * 64 + w4 * 4) = v;
        }
    }
}

// ---------------- aggregate (R10 proven core): warp/node, lane = 4 cols ----
__device__ __forceinline__ void bf2_fma(float4& acc, uint2 p, float w) {
    float2 lo = __bfloat1622float2(*(__nv_bfloat162*)&p.x);
    float2 hi = __bfloat1622float2(*(__nv_bfloat162*)&p.y);
    acc.x += lo.x * w; acc.y += lo.y * w; acc.z += hi.x * w; acc.w += hi.y * w;
}

__device__ __forceinline__ float4 aggregate_row(int node, int lane,
                                                const float* __restrict__ b) {
    int beg = __ldg(&g_row_ptr[node]);
    int end = __ldg(&g_row_ptr[node + 1]);
    float di = __ldg(&g_dinv[node]);
    float sw = di * di;   // self-loop weight

    float4 acc = ((const float4*)b)[lane];
    uint2 ts = *(const uint2*)(g_Th + (size_t)node * 64 + lane * 2);
    bf2_fma(acc, ts, sw);

    int e = beg;
    for (; e + 4 <= end; e += 4) {
        int2 c0 = __ldg(&g_col[e + 0]);
        int2 c1 = __ldg(&g_col[e + 1]);
        int2 c2 = __ldg(&g_col[e + 2]);
        int2 c3 = __ldg(&g_col[e + 3]);
        uint2 v0 = *(const uint2*)(g_Th + (size_t)c0.x * 64 + lane * 2);
        uint2 v1 = *(const uint2*)(g_Th + (size_t)c1.x * 64 + lane * 2);
        uint2 v2 = *(const uint2*)(g_Th + (size_t)c2.x * 64 + lane * 2);
        uint2 v3 = *(const uint2*)(g_Th + (size_t)c3.x * 64 + lane * 2);
        bf2_fma(acc, v0, __int_as_float(c0.y));
        bf2_fma(acc, v1, __int_as_float(c1.y));
        bf2_fma(acc, v2, __int_as_float(c2.y));
        bf2_fma(acc, v3, __int_as_float(c3.y));
    }
    for (; e < end; e++) {
        int2 c = __ldg(&g_col[e]);
        uint2 v = *(const uint2*)(g_Th + (size_t)c.x * 64 + lane * 2);
        bf2_fma(acc, v, __int_as_float(c.y));
    }
    return acc;
}

// layers 0-2: write bf16 A
__global__ void k_aggregate(const float* __restrict__ b) {
    int node = (blockIdx.x * blockDim.x + threadIdx.x) >> 5;
    int lane = threadIdx.x & 31;
    if (node >= N_NODES) return;
    float4 acc = aggregate_row(node, lane, b);
    uint2 p;
    p.x = pack_bf16x2(acc.x, acc.y);
    p.y = pack_bf16x2(acc.z, acc.w);
    *(uint2*)(g_Ah + (size_t)node * 64 + lane * 2) = p;
}

// layer 3: relu + pool directly (skip A round-trip)
__global__ void k_aggregate_pool(const float* __restrict__ b,
                                 const int* __restrict__ batch) {
    int node = (blockIdx.x * blockDim.x + threadIdx.x) >> 5;
    int lane = threadIdx.x & 31;
    if (node >= N_NODES) return;
    float4 acc = aggregate_row(node, lane, b);
    acc.x = fmaxf(acc.x, 0.f); acc.y = fmaxf(acc.y, 0.f);
    acc.z = fmaxf(acc.z, 0.f); acc.w = fmaxf(acc.w, 0.f);
    int g = __ldg(&batch[node]);
    float* d = g_pool + g * HID + lane * 4;
    asm volatile("red.global.add.v4.f32 [%0], {%1,%2,%3,%4};"
                 :: "l"(d), "f"(acc.x), "f"(acc.y), "f"(acc.z), "f"(acc.w) : "memory");
    if (lane == 0) atomicAdd(&g_cnt[g], 1.0f);
}

// ---------------- pooling buffers ----------------
__global__ void k_zero_pool() {
    int i = blockIdx.x * blockDim.x + threadIdx.x;
    if (i < N_GRAPHS * HID) g_pool[i] = 0.f;
    if (i < N_GRAPHS) g_cnt[i] = 0.f;
}

// ---------------- head ----------------
__global__ void k_final(const float* __restrict__ Wc, const float* __restrict__ bc,
                        float* __restrict__ out) {
    int g = blockIdx.x;
    int c = threadIdx.x;     // 128
    float cn = fmaxf(g_cnt[g], 1.0f);
    float v = g_pool[g * HID + c] / cn * Wc[c];
    #pragma unroll
    for (int o = 16; o > 0; o >>= 1) v += __shfl_down_sync(0xffffffffu, v, o);
    __shared__ float ss[4];
    if ((c & 31) == 0) ss[c >> 5] = v;
    __syncthreads();
    if (c == 0) {
        float s = ss[0] + ss[1] + ss[2] + ss[3] + bc[0];
        out[g] = 1.0f / (1.0f + expf(-s));
    }
}

// ---------------- launch ----------------
extern "C" void kernel_launch(void* const* d_in, const int* in_sizes, int n_in,
                              void* d_out, int out_size) {
    const float* x   = (const float*)d_in[0];
    const int*   ei  = (const int*)d_in[1];
    const float* ew  = (const float*)d_in[2];
    const int*   bat = (const int*)d_in[3];
    const float* W[4]  = { (const float*)d_in[4], (const float*)d_in[6],
                           (const float*)d_in[8], (const float*)d_in[10] };
    const float* B[4]  = { (const float*)d_in[5], (const float*)d_in[7],
                           (const float*)d_in[9], (const float*)d_in[11] };
    const float* Wc  = (const float*)d_in[12];
    const float* bc  = (const float*)d_in[13];
    float* out = (float*)d_out;

    cudaFuncSetAttribute(k_gemm_mma, cudaFuncAttributeMaxDynamicSharedMemorySize,
                         GEMM_SMEM);

    // ---- preprocessing: degrees + CSR build + W fragments + pool zero ----
    k_init_deg<<<(N_NODES + 255) / 256, 256>>>();
    k_accum_deg<<<(N_EDGES + 255) / 256, 256>>>(ei, ew);
    k_dinv<<<(N_NODES + 255) / 256, 256>>>();
    k_scan1<<<SCAN_BLK, 256>>>();
    k_scan2<<<1, 512>>>();
    k_scan3<<<SCAN_BLK, 256>>>();
    k_fill<<<(N_EDGES + 255) / 256, 256>>>(ei, ew);
    k_wfrag<<<64, 256>>>(W[0], W[1], W[2], W[3]);
    k_zero_pool<<<(N_GRAPHS * HID + 255) / 256, 256>>>();

    const int gemm_grid = (N_NODES + GTILE - 1) / GTILE;     // 782
    const int aggr_grid = (N_NODES * 32 + 255) / 256;        // warp per node

    // ---- 4 GCN layers (last one fuses relu+pool) ----
    for (int l = 0; l < 4; l++) {
        k_gemm_mma<<<gemm_grid, 256, GEMM_SMEM>>>(x, l);
        if (l < 3)
            k_aggregate<<<aggr_grid, 256>>>(B[l]);
        else
            k_aggregate_pool<<<aggr_grid, 256>>>(B[l], bat);
    }

    // ---- head ----
    k_final<<<N_GRAPHS, HID>>>(Wc, bc, out);
}

// round 15
// speedup vs baseline: 1.8527x; 1.0259x over previous
#include <cuda_runtime.h>
#include <cuda_bf16.h>
#include <cstdint>

#define N_NODES 100000
#define N_EDGES 3200000
#define HID 128
#define N_GRAPHS 512

// ---------------- scratch (device globals; no allocation allowed) ----------
__device__ uint32_t g_Th[(size_t)N_NODES * 64];  // T as packed bf16x2 (128 cols)
__device__ uint32_t g_Ah[(size_t)N_NODES * 64];  // A as packed bf16x2
__device__ unsigned long long g_dh[N_NODES];     // packed: count<<44 | fx32 ew-sum
__device__ float g_dinv[N_NODES];
__device__ float g_pool[N_GRAPHS * HID];
__device__ float g_cnt[N_GRAPHS];
// CSR (by destination) — interleaved (src, weight_bits)
__device__ int   g_row_ptr[N_NODES + 1];
__device__ int   g_row_fill[N_NODES];
__device__ int2  g_col[N_EDGES];

#define SCAN_BLK 391            // ceil(100000/256)
__device__ int   g_bsum[512];   // block sums (padded)

// bf16 B-fragments for all 4 layers (m16n8k16):
// [layer][s(8)][t(16)][lane(32)] -> uint2 = (b0 = W[k0+2tg..+1][n], b1 = W[k0+8+2tg..+1][n])
__device__ uint2 g_Wfrag[4 * 8 * 16 * 32];

__device__ __forceinline__ uint32_t pack_bf16x2(float a, float b) {
    __nv_bfloat162 h = __float22bfloat162_rn(make_float2(a, b));
    return *(uint32_t*)&h;
}

__device__ __forceinline__ int hist_of(unsigned long long v) {
    return (int)(v >> 44);
}

// ---------------- init: zero packed deg/hist + pool buffers ----------------
__global__ void k_init() {
    int i = blockIdx.x * blockDim.x + threadIdx.x;
    if (i < N_NODES) g_dh[i] = 0ull;
    if (i < N_GRAPHS * HID) g_pool[i] = 0.f;
    if (i < N_GRAPHS) g_cnt[i] = 0.f;
}

// ---------------- degree+hist: ONE u64 atomic per edge ---------------------
__global__ void k_accum_deg(const int* __restrict__ ei, const float* __restrict__ ew) {
    int e = blockIdx.x * blockDim.x + threadIdx.x;
    if (e >= N_EDGES) return;
    int dst = ei[N_EDGES + e];
    unsigned long long pk = (1ull << 44)
        + (unsigned long long)((double)ew[e] * 4294967296.0);
    atomicAdd(&g_dh[dst], pk);
}

// ---------------- 3-phase parallel exclusive scan (+ fused dinv) -----------
__global__ void k_scan1() {
    __shared__ int sh[256];
    int i = blockIdx.x * 256 + threadIdx.x;
    int v = 0;
    if (i < N_NODES) {
        unsigned long long d = g_dh[i];
        v = hist_of(d);
        // deg = 1 (self-loop) + fixed-point edge-weight sum
        float deg = 1.0f + (float)((double)(d & ((1ull << 44) - 1)) * (1.0 / 4294967296.0));
        g_dinv[i] = rsqrtf(deg);
    }
    sh[threadIdx.x] = v;
    __syncthreads();
    #pragma unroll
    for (int o = 128; o > 0; o >>= 1) {
        if (threadIdx.x < o) sh[threadIdx.x] += sh[threadIdx.x + o];
        __syncthreads();
    }
    if (threadIdx.x == 0) g_bsum[blockIdx.x] = sh[0];
}

__global__ void k_scan2() {
    __shared__ int sh[512];
    int t = threadIdx.x;
    sh[t] = (t < SCAN_BLK) ? g_bsum[t] : 0;
    __syncthreads();
    #pragma unroll
    for (int o = 1; o < 512; o <<= 1) {
        int v = (t >= o) ? sh[t - o] : 0;
        __syncthreads();
        sh[t] += v;
        __syncthreads();
    }
    if (t < SCAN_BLK) g_bsum[t] = (t == 0) ? 0 : sh[t - 1];   // exclusive
}

__global__ void k_scan3() {
    __shared__ int sh[256];
    int t = threadIdx.x;
    int i = blockIdx.x * 256 + t;
    int v = (i < N_NODES) ? hist_of(g_dh[i]) : 0;
    sh[t] = v;
    __syncthreads();
    #pragma unroll
    for (int o = 1; o < 256; o <<= 1) {
        int u = (t >= o) ? sh[t - o] : 0;
        __syncthreads();
        sh[t] += u;
        __syncthreads();
    }
    if (i < N_NODES) {
        int off = g_bsum[blockIdx.x] + sh[t] - v;   // exclusive
        g_row_ptr[i] = off;
        g_row_fill[i] = off;
    }
    if (i == 0) g_row_ptr[N_NODES] = N_EDGES;
}

// ---------------- fill CSR: interleaved (src, norm-weight) -----------------
__global__ void k_fill(const int* __restrict__ ei, const float* __restrict__ ew) {
    int e = blockIdx.x * blockDim.x + threadIdx.x;
    if (e >= N_EDGES) return;
    int src = ei[e], dst = ei[N_EDGES + e];
    int pos = atomicAdd(&g_row_fill[dst], 1);
    float w = g_dinv[src] * ew[e] * g_dinv[dst];
    g_col[pos] = make_int2(src, __float_as_int(w));
}

// ---------------- precompute W bf16 fragments (all 4 layers) ---------------
__global__ void k_wfrag(const float* __restrict__ W0, const float* __restrict__ W1,
                        const float* __restrict__ W2, const float* __restrict__ W3) {
    int idx = blockIdx.x * 256 + threadIdx.x;     // 4*8*16*32 = 16384
    if (idx >= 4 * 8 * 16 * 32) return;
    int layer = idx >> 12;
    int rem = idx & 4095;
    int s = rem >> 9;            // k-step (0..7), K=16 each
    int t = (rem >> 5) & 15;     // n-tile (0..15)
    int lane = rem & 31;
    int tg = lane & 3, gid = lane >> 2;
    const float* W = (layer == 0) ? W0 : (layer == 1) ? W1 : (layer == 2) ? W2 : W3;
    int n = t * 8 + gid;
    int k0 = s * 16;
    uint2 v;
    v.x = pack_bf16x2(W[(k0 + 2 * tg) * HID + n],     W[(k0 + 2 * tg + 1) * HID + n]);
    v.y = pack_bf16x2(W[(k0 + 8 + 2 * tg) * HID + n], W[(k0 + 9 + 2 * tg) * HID + n]);
    g_Wfrag[idx] = v;
}

// ---------------- GEMM via mma.sync bf16 m16n8k16: Th = bf16(act(in) @ W) --
#define GTILE 128
#define XS_STRIDE 68   // bf16x2 words per row (64 + pad 4); conflict-free
#define GEMM_SMEM (GTILE * XS_STRIDE * 4)

__device__ __forceinline__ void mma_bf16(float* d, uint32_t a0, uint32_t a1,
                                         uint32_t a2, uint32_t a3,
                                         uint32_t b0, uint32_t b1) {
    asm volatile(
        "mma.sync.aligned.m16n8k16.row.col.f32.bf16.bf16.f32 "
        "{%0,%1,%2,%3}, {%4,%5,%6,%7}, {%8,%9}, {%0,%1,%2,%3};"
        : "+f"(d[0]), "+f"(d[1]), "+f"(d[2]), "+f"(d[3])
        : "r"(a0), "r"(a1), "r"(a2), "r"(a3), "r"(b0), "r"(b1));
}

__global__ void __launch_bounds__(256) k_gemm_mma(const float* __restrict__ X,
                                                  int layer) {
    extern __shared__ uint32_t Xs[];   // [128][68] bf16x2 words; reused as out stage
    int tid = threadIdx.x;
    int wid = tid >> 5;
    int lane = tid & 31;
    int row0 = blockIdx.x * GTILE;

    // stage input tile as bf16x2 (FULL 128 cols = 32 word-pairs per row):
    // layer 0 = fp32 x; layers 1-3 = bf16 A (+relu)
    #pragma unroll
    for (int it = 0; it < 16; it++) {
        int i = tid + it * 256;            // i in [0,4096): row = i>>5, wp = i&31
        int row = i >> 5;
        int wp = i & 31;                   // word-pair -> cols 4wp..4wp+3
        int grow = row0 + row;
        uint32_t w0 = 0, w1 = 0;
        if (grow < N_NODES) {
            if (layer == 0) {
                float4 v = *(const float4*)(X + (size_t)grow * HID + wp * 4);
                w0 = pack_bf16x2(v.x, v.y);
                w1 = pack_bf16x2(v.z, v.w);
            } else {
                uint2 p = *(const uint2*)(g_Ah + (size_t)grow * 64 + wp * 2);
                float2 lo = __bfloat1622float2(*(__nv_bfloat162*)&p.x);
                float2 hi = __bfloat1622float2(*(__nv_bfloat162*)&p.y);
                w0 = pack_bf16x2(fmaxf(lo.x, 0.f), fmaxf(lo.y, 0.f));
                w1 = pack_bf16x2(fmaxf(hi.x, 0.f), fmaxf(hi.y, 0.f));
            }
        }
        Xs[row * XS_STRIDE + wp * 2]     = w0;
        Xs[row * XS_STRIDE + wp * 2 + 1] = w1;
    }
    __syncthreads();

    int tg = lane & 3, gid = lane >> 2;
    float acc[16][4];
    #pragma unroll
    for (int t = 0; t < 16; t++)
        #pragma unroll
        for (int j = 0; j < 4; j++) acc[t][j] = 0.f;

    const uint32_t* arow_lo = Xs + (wid * 16 + gid) * XS_STRIDE;
    const uint32_t* arow_hi = arow_lo + 8 * XS_STRIDE;
    const uint2* frag = g_Wfrag + (size_t)layer * 4096 + lane;

    #pragma unroll
    for (int s = 0; s < 8; s++) {
        int kw = s * 8;   // word base for this k-step (16 cols = 8 words)
        uint32_t a0 = arow_lo[kw + tg];
        uint32_t a1 = arow_hi[kw + tg];
        uint32_t a2 = arow_lo[kw + 4 + tg];
        uint32_t a3 = arow_hi[kw + 4 + tg];
        const uint2* f = frag + s * 512;   // [t][lane] stride 32
        #pragma unroll
        for (int t = 0; t < 16; t++) {
            uint2 b = f[t * 32];
            mma_bf16(acc[t], a0, a1, a2, a3, b.x, b.y);
        }
    }

    // epilogue: stage bf16x2 rows in smem (conflict-free), then coalesced STG
    __syncthreads();   // all warps done reading Xs
    uint32_t* St = Xs; // reuse: [128][XS_STRIDE]
    int lrow_lo = wid * 16 + gid;
    #pragma unroll
    for (int t = 0; t < 16; t++) {
        int widx = t * 4 + tg;
        St[lrow_lo * XS_STRIDE + widx]       = pack_bf16x2(acc[t][0], acc[t][1]);
        St[(lrow_lo + 8) * XS_STRIDE + widx] = pack_bf16x2(acc[t][2], acc[t][3]);
    }
    __syncthreads();
    // copy 128 rows x 64 words = 2048 uint4 -> fully coalesced in g_Th
    #pragma unroll
    for (int it = 0; it < 8; it++) {
        int j = tid + it * 256;        // j in [0,2048): row = j>>4, w4 = j&15
        int row = j >> 4;
        int w4 = j & 15;
        int grow = row0 + row;
        if (grow < N_NODES) {
            uint4 v = *(const uint4*)&St[row * XS_STRIDE + w4 * 4];
            *(uint4*)(g_Th + (size_t)grow * 64 + w4 * 4) = v;
        }
    }
}

// ---------------- aggregate (R10 proven core): warp/node, lane = 4 cols ----
__device__ __forceinline__ void bf2_fma(float4& acc, uint2 p, float w) {
    float2 lo = __bfloat1622float2(*(__nv_bfloat162*)&p.x);
    float2 hi = __bfloat1622float2(*(__nv_bfloat162*)&p.y);
    acc.x += lo.x * w; acc.y += lo.y * w; acc.z += hi.x * w; acc.w += hi.y * w;
}

__device__ __forceinline__ float4 aggregate_row(int node, int lane,
                                                const float* __restrict__ b) {
    int beg = __ldg(&g_row_ptr[node]);
    int end = __ldg(&g_row_ptr[node + 1]);
    float di = __ldg(&g_dinv[node]);
    float sw = di * di;   // self-loop weight

    float4 acc = ((const float4*)b)[lane];
    uint2 ts = *(const uint2*)(g_Th + (size_t)node * 64 + lane * 2);
    bf2_fma(acc, ts, sw);

    int e = beg;
    for (; e + 4 <= end; e += 4) {
        int2 c0 = __ldg(&g_col[e + 0]);
        int2 c1 = __ldg(&g_col[e + 1]);
        int2 c2 = __ldg(&g_col[e + 2]);
        int2 c3 = __ldg(&g_col[e + 3]);
        uint2 v0 = *(const uint2*)(g_Th + (size_t)c0.x * 64 + lane * 2);
        uint2 v1 = *(const uint2*)(g_Th + (size_t)c1.x * 64 + lane * 2);
        uint2 v2 = *(const uint2*)(g_Th + (size_t)c2.x * 64 + lane * 2);
        uint2 v3 = *(const uint2*)(g_Th + (size_t)c3.x * 64 + lane * 2);
        bf2_fma(acc, v0, __int_as_float(c0.y));
        bf2_fma(acc, v1, __int_as_float(c1.y));
        bf2_fma(acc, v2, __int_as_float(c2.y));
        bf2_fma(acc, v3, __int_as_float(c3.y));
    }
    for (; e < end; e++) {
        int2 c = __ldg(&g_col[e]);
        uint2 v = *(const uint2*)(g_Th + (size_t)c.x * 64 + lane * 2);
        bf2_fma(acc, v, __int_as_float(c.y));
    }
    return acc;
}

// layers 0-2: write bf16 A
__global__ void k_aggregate(const float* __restrict__ b) {
    int node = (blockIdx.x * blockDim.x + threadIdx.x) >> 5;
    int lane = threadIdx.x & 31;
    if (node >= N_NODES) return;
    float4 acc = aggregate_row(node, lane, b);
    uint2 p;
    p.x = pack_bf16x2(acc.x, acc.y);
    p.y = pack_bf16x2(acc.z, acc.w);
    *(uint2*)(g_Ah + (size_t)node * 64 + lane * 2) = p;
}

// layer 3: relu + pool directly (skip A round-trip)
__global__ void k_aggregate_pool(const float* __restrict__ b,
                                 const int* __restrict__ batch) {
    int node = (blockIdx.x * blockDim.x + threadIdx.x) >> 5;
    int lane = threadIdx.x & 31;
    if (node >= N_NODES) return;
    float4 acc = aggregate_row(node, lane, b);
    acc.x = fmaxf(acc.x, 0.f); acc.y = fmaxf(acc.y, 0.f);
    acc.z = fmaxf(acc.z, 0.f); acc.w = fmaxf(acc.w, 0.f);
    int g = __ldg(&batch[node]);
    float* d = g_pool + g * HID + lane * 4;
    asm volatile("red.global.add.v4.f32 [%0], {%1,%2,%3,%4};"
                 :: "l"(d), "f"(acc.x), "f"(acc.y), "f"(acc.z), "f"(acc.w) : "memory");
    if (lane == 0) atomicAdd(&g_cnt[g], 1.0f);
}

// ---------------- head ----------------
__global__ void k_final(const float* __restrict__ Wc, const float* __restrict__ bc,
                        float* __restrict__ out) {
    int g = blockIdx.x;
    int c = threadIdx.x;     // 128
    float cn = fmaxf(g_cnt[g], 1.0f);
    float v = g_pool[g * HID + c] / cn * Wc[c];
    #pragma unroll
    for (int o = 16; o > 0; o >>= 1) v += __shfl_down_sync(0xffffffffu, v, o);
    __shared__ float ss[4];
    if ((c & 31) == 0) ss[c >> 5] = v;
    __syncthreads();
    if (c == 0) {
        float s = ss[0] + ss[1] + ss[2] + ss[3] + bc[0];
        out[g] = 1.0f / (1.0f + expf(-s));
    }
}

// ---------------- launch ----------------
extern "C" void kernel_launch(void* const* d_in, const int* in_sizes, int n_in,
                              void* d_out, int out_size) {
    const float* x   = (const float*)d_in[0];
    const int*   ei  = (const int*)d_in[1];
    const float* ew  = (const float*)d_in[2];
    const int*   bat = (const int*)d_in[3];
    const float* W[4]  = { (const float*)d_in[4], (const float*)d_in[6],
                           (const float*)d_in[8], (const float*)d_in[10] };
    const float* B[4]  = { (const float*)d_in[5], (const float*)d_in[7],
                           (const float*)d_in[9], (const float*)d_in[11] };
    const float* Wc  = (const float*)d_in[12];
    const float* bc  = (const float*)d_in[13];
    float* out = (float*)d_out;

    cudaFuncSetAttribute(k_gemm_mma, cudaFuncAttributeMaxDynamicSharedMemorySize,
                         GEMM_SMEM);

    // ---- preprocessing: init + degrees + CSR build + W fragments ----
    k_init<<<(N_NODES + 255) / 256, 256>>>();        // covers pool too (65536<100000)
    k_accum_deg<<<(N_EDGES + 255) / 256, 256>>>(ei, ew);
    k_scan1<<<SCAN_BLK, 256>>>();                    // fused dinv
    k_scan2<<<1, 512>>>();
    k_scan3<<<SCAN_BLK, 256>>>();
    k_fill<<<(N_EDGES + 255) / 256, 256>>>(ei, ew);
    k_wfrag<<<64, 256>>>(W[0], W[1], W[2], W[3]);

    const int gemm_grid = (N_NODES + GTILE - 1) / GTILE;     // 782
    const int aggr_grid = (N_NODES * 32 + 255) / 256;        // warp per node

    // ---- 4 GCN layers (last one fuses relu+pool) ----
    for (int l = 0; l < 4; l++) {
        k_gemm_mma<<<gemm_grid, 256, GEMM_SMEM>>>(x, l);
        if (l < 3)
            k_aggregate<<<aggr_grid, 256>>>(B[l]);
        else
            k_aggregate_pool<<<aggr_grid, 256>>>(B[l], bat);
    }

    // ---- head ----
    k_final<<<N_GRAPHS, HID>>>(Wc, bc, out);
}